// round 4
// baseline (speedup 1.0000x reference)
#include <cuda_runtime.h>

#define Bb     8
#define Nn     3136
#define Cc     64
#define CI     32
#define BNROWS 25088          // Bb * Nn
#define LAMF   0.1f
#define HSTEP  0.05f
#define BNEPS  1e-3f
#define INVN   (1.0f / 3136.0f)

// ---- scratch (static device globals; zero-init at load, self-cleaning) ----
__device__ float d_theta[BNROWS * CI];
__device__ float d_phi[BNROWS * CI];
__device__ float d_phisum[Bb * CI];
__device__ float d_pspart[784 * CI];        // per-block phi-sum partials
__device__ float d_Mbuf[2][Bb * 2048];      // atomic accum, re-zeroed by tails
__device__ float d_MW[2][Bb * 2048];        // (lam/N) * M @ W[iter]
__device__ float d_g1[BNROWS * Cc];
__device__ unsigned d_cnt1[Bb];             // self-resetting
__device__ unsigned d_cnt2[Bb];

// ===========================================================================
// K1: theta/phi GEMM + partial M0 = phi^T x (atomic) + phisum partials.
// Tail (last block per batch): phisum final, MW0 = (lam/N) M0 @ W0, zero M0.
// 32 rows/block, grid 784 (98 blocks per batch).
__global__ void __launch_bounds__(256) k_front(
        const float* __restrict__ x,
        const float* __restrict__ Wt, const float* __restrict__ bt,
        const float* __restrict__ Wp, const float* __restrict__ bp,
        const float* __restrict__ Wst) {
    __shared__ float sm[7488];
    float* SX  = sm;            // 32*64  = 2048
    float* SWT = sm + 2048;     // 32*68  = 2176
    float* SWP = sm + 4224;     // 32*68  = 2176
    float* SPH = sm + 6400;     // 32*33  = 1056
    float* SP  = sm + 7456;     // 32
    __shared__ unsigned s_old;

    int t  = threadIdx.x;
    int gb = blockIdx.x;
    int b  = gb / 98;
    int r0 = gb * 32;

    {
        const float4* src = (const float4*)(x + r0 * 64);
        ((float4*)SX)[t]       = src[t];
        ((float4*)SX)[t + 256] = src[t + 256];
    }
    for (int e = t; e < 2048; e += 256) {
        int k = e >> 5, d = e & 31;
        SWT[d * 68 + k] = Wt[e];
        SWP[d * 68 + k] = Wp[e];
    }
    if (t < 32) SP[t] = 0.f;
    __syncthreads();

    int w = t >> 5, d = t & 31;
    float th[4], ph[4];
    float bt_d = bt[d], bp_d = bp[d];
#pragma unroll
    for (int j = 0; j < 4; j++) { th[j] = bt_d; ph[j] = bp_d; }

    const float* xr = SX + w * 4 * 64;
    const float* wt = SWT + d * 68;
    const float* wp = SWP + d * 68;
#pragma unroll
    for (int k = 0; k < 64; k += 4) {
        float4 a = *(const float4*)(wt + k);
        float4 bv = *(const float4*)(wp + k);
#pragma unroll
        for (int j = 0; j < 4; j++) {
            float4 xv = *(const float4*)(xr + j * 64 + k);
            th[j] = fmaf(xv.x, a.x, th[j]);  th[j] = fmaf(xv.y, a.y, th[j]);
            th[j] = fmaf(xv.z, a.z, th[j]);  th[j] = fmaf(xv.w, a.w, th[j]);
            ph[j] = fmaf(xv.x, bv.x, ph[j]); ph[j] = fmaf(xv.y, bv.y, ph[j]);
            ph[j] = fmaf(xv.z, bv.z, ph[j]); ph[j] = fmaf(xv.w, bv.w, ph[j]);
        }
    }
    int r = r0 + w * 4;
    float phs = 0.f;
#pragma unroll
    for (int j = 0; j < 4; j++) {
        d_theta[(r + j) * 32 + d] = th[j];
        d_phi[(r + j) * 32 + d]   = ph[j];
        SPH[(w * 4 + j) * 33 + d] = ph[j];
        phs += ph[j];
    }
    atomicAdd(&SP[d], phs);
    __syncthreads();
    if (t < 32) d_pspart[gb * 32 + t] = SP[t];

    // ---- partial M0 = phi_chunk^T @ x_chunk ----
    int d2 = t & 31, cb = (t >> 5) * 8;
    float acc[8] = {0.f, 0.f, 0.f, 0.f, 0.f, 0.f, 0.f, 0.f};
#pragma unroll 8
    for (int rr = 0; rr < 32; rr++) {
        float pd = SPH[rr * 33 + d2];
        float4 g0 = *(const float4*)(SX + rr * 64 + cb);
        float4 g1v = *(const float4*)(SX + rr * 64 + cb + 4);
        acc[0] = fmaf(pd, g0.x, acc[0]);  acc[1] = fmaf(pd, g0.y, acc[1]);
        acc[2] = fmaf(pd, g0.z, acc[2]);  acc[3] = fmaf(pd, g0.w, acc[3]);
        acc[4] = fmaf(pd, g1v.x, acc[4]); acc[5] = fmaf(pd, g1v.y, acc[5]);
        acc[6] = fmaf(pd, g1v.z, acc[6]); acc[7] = fmaf(pd, g1v.w, acc[7]);
    }
    {
        float* Mb = d_Mbuf[0] + b * 2048 + d2 * 64 + cb;
#pragma unroll
        for (int q = 0; q < 8; q++) atomicAdd(&Mb[q], acc[q]);
    }

    __threadfence();
    __syncthreads();
    if (t == 0) s_old = atomicAdd(&d_cnt1[b], 1u);
    __syncthreads();
    if (s_old != 97u) return;

    // ---- TAIL: last block of this batch ----
    __threadfence();
    if (t < 32) {
        float a = 0.f;
        for (int j = 0; j < 98; j++) a += d_pspart[(b * 98 + j) * 32 + t];
        d_phisum[b * 32 + t] = a;
    }
    // stage W0 and M0 (smem fully dead now)
    float* SW = sm;            // 64*68 = 4352
    float* SM = sm + 4352;     // 2048
    for (int e = t; e < 1024; e += 256) {
        int k = e >> 4, c4 = (e & 15) * 4;
        *(float4*)(SW + k * 68 + c4) = ((const float4*)Wst)[e];
    }
    for (int e = t; e < 2048; e += 256) {
        SM[e] = d_Mbuf[0][b * 2048 + e];
        d_Mbuf[0][b * 2048 + e] = 0.f;      // self-clean for next replay
    }
    if (t == 0) d_cnt1[b] = 0u;             // self-reset
    __syncthreads();

    int dd = t >> 3, c0 = (t & 7) * 8;
    float a2[8] = {0.f, 0.f, 0.f, 0.f, 0.f, 0.f, 0.f, 0.f};
#pragma unroll 8
    for (int c = 0; c < 64; c++) {
        float m = SM[dd * 64 + c];
        float4 w0 = *(const float4*)(SW + c * 68 + c0);
        float4 w1 = *(const float4*)(SW + c * 68 + c0 + 4);
        a2[0] = fmaf(m, w0.x, a2[0]); a2[1] = fmaf(m, w0.y, a2[1]);
        a2[2] = fmaf(m, w0.z, a2[2]); a2[3] = fmaf(m, w0.w, a2[3]);
        a2[4] = fmaf(m, w1.x, a2[4]); a2[5] = fmaf(m, w1.y, a2[5]);
        a2[6] = fmaf(m, w1.z, a2[6]); a2[7] = fmaf(m, w1.w, a2[7]);
    }
    float* o = d_MW[0] + b * 2048 + dd * 64 + c0;
    const float sc = LAMF * INVN;
#pragma unroll
    for (int q = 0; q < 8; q++) o[q] = sc * a2[q];
}

// ===========================================================================
// K2: apply iteration 0 (K=96 GEMM epilogue) -> g1, plus partial M1 = phi^T g1
// (atomic). Tail per batch: MW1 = (lam/N) M1 @ W1, zero M1, reset counter.
// 64 rows/block, grid 392 (49 per batch).
__global__ void __launch_bounds__(256) k_apply_fused(
        const float* __restrict__ x,
        const float* __restrict__ Wst, const float* __restrict__ bst,
        const float* __restrict__ gam, const float* __restrict__ bet,
        const float* __restrict__ mmean, const float* __restrict__ mvar) {
    __shared__ float sm2[13152];
    float* sAt = sm2;              // 96*68 = 6528  (A^T: [k][row])
    float* sB  = sm2 + 6528;       // 96*68 = 6528  ([k][col])
    float* ss  = sm2 + 13056;      // 64
    float* sps = sm2 + 13120;      // 32
    __shared__ unsigned s_old;

    int t  = threadIdx.x;
    int r0 = blockIdx.x * 64;
    int b  = blockIdx.x / 49;

    // stage theta -> sAt rows [0,32)
#pragma unroll
    for (int j = 0; j < 2; j++) {
        int e = t + j * 256;
        int r = e >> 3, dd = (e & 7) * 4;
        float4 v = ((const float4*)(d_theta + r0 * 32))[e];
        sAt[(dd + 0) * 68 + r] = v.x;
        sAt[(dd + 1) * 68 + r] = v.y;
        sAt[(dd + 2) * 68 + r] = v.z;
        sAt[(dd + 3) * 68 + r] = v.w;
    }
    // stage B: rows [0,32) = MW0, rows [32,96) = W0
    const float* MWi = d_MW[0] + b * 2048;
    const float* Wi  = Wst;
#pragma unroll
    for (int j = 0; j < 6; j++) {
        int e = t + j * 256;
        if (e < 512) {
            int k = e >> 4, c4 = (e & 15) * 4;
            *(float4*)(sB + k * 68 + c4) = ((const float4*)MWi)[e];
        } else {
            int e2 = e - 512;
            int k = e2 >> 4, c4 = (e2 & 15) * 4;
            *(float4*)(sB + (32 + k) * 68 + c4) = ((const float4*)Wi)[e2];
        }
    }
    if (t < 32) sps[t] = d_phisum[b * 32 + t];
    __syncthreads();

    if (t < 64) {
        float a = 0.f;
#pragma unroll
        for (int k = 0; k < 32; k++) a = fmaf(sAt[k * 68 + t], sps[k], a);
        ss[t] = a * (-LAMF * INVN);
    }
    __syncthreads();

    // stage scaled g(=x) -> sAt rows [32,96)
#pragma unroll
    for (int j = 0; j < 4; j++) {
        int e = t + j * 256;
        int r = e >> 4, c4 = (e & 15) * 4;
        float4 v = ((const float4*)(x + r0 * 64))[e];
        float sc = ss[r];
        sAt[(32 + c4 + 0) * 68 + r] = v.x * sc;
        sAt[(32 + c4 + 1) * 68 + r] = v.y * sc;
        sAt[(32 + c4 + 2) * 68 + r] = v.z * sc;
        sAt[(32 + c4 + 3) * 68 + r] = v.w * sc;
    }
    __syncthreads();

    int tx = t & 15, ty = t >> 4;
    int rr = ty * 4, cc = tx * 4;
    float acc[4][4];
#pragma unroll
    for (int i = 0; i < 4; i++)
#pragma unroll
        for (int j = 0; j < 4; j++) acc[i][j] = 0.f;

#pragma unroll 8
    for (int k = 0; k < 96; k++) {
        float4 a = *(const float4*)(sAt + k * 68 + rr);
        float4 bv = *(const float4*)(sB + k * 68 + cc);
        acc[0][0] = fmaf(a.x, bv.x, acc[0][0]); acc[0][1] = fmaf(a.x, bv.y, acc[0][1]);
        acc[0][2] = fmaf(a.x, bv.z, acc[0][2]); acc[0][3] = fmaf(a.x, bv.w, acc[0][3]);
        acc[1][0] = fmaf(a.y, bv.x, acc[1][0]); acc[1][1] = fmaf(a.y, bv.y, acc[1][1]);
        acc[1][2] = fmaf(a.y, bv.z, acc[1][2]); acc[1][3] = fmaf(a.y, bv.w, acc[1][3]);
        acc[2][0] = fmaf(a.z, bv.x, acc[2][0]); acc[2][1] = fmaf(a.z, bv.y, acc[2][1]);
        acc[2][2] = fmaf(a.z, bv.z, acc[2][2]); acc[2][3] = fmaf(a.z, bv.w, acc[2][3]);
        acc[3][0] = fmaf(a.w, bv.x, acc[3][0]); acc[3][1] = fmaf(a.w, bv.y, acc[3][1]);
        acc[3][2] = fmaf(a.w, bv.z, acc[3][2]); acc[3][3] = fmaf(a.w, bv.w, acc[3][3]);
    }
    __syncthreads();   // sAt/sB dead; safe to reuse below

    float* SOUT = sm2;           // 64*68 = 4352
    float* SPHI = sm2 + 6528;    // 64*33 = 2112

    // epilogue + write g1 + stash out tile in smem
    {
        float4 bias = *(const float4*)(bst + cc);
        float4 gm   = *(const float4*)(gam + cc);
        float4 bt4  = *(const float4*)(bet + cc);
        float4 mmv  = *(const float4*)(mmean + cc);
        float4 mv   = *(const float4*)(mvar + cc);
        float scl[4] = { gm.x * rsqrtf(mv.x + BNEPS), gm.y * rsqrtf(mv.y + BNEPS),
                         gm.z * rsqrtf(mv.z + BNEPS), gm.w * rsqrtf(mv.w + BNEPS) };
        float bia[4]  = { bias.x, bias.y, bias.z, bias.w };
        float mean[4] = { mmv.x, mmv.y, mmv.z, mmv.w };
        float betc[4] = { bt4.x, bt4.y, bt4.z, bt4.w };
#pragma unroll
        for (int i = 0; i < 4; i++) {
            int r = r0 + rr + i;
            float4 xv = *(const float4*)(x + r * 64 + cc);
            float xa[4] = { xv.x, xv.y, xv.z, xv.w };
            float4 ov;
            float* op = (float*)&ov;
#pragma unroll
            for (int j = 0; j < 4; j++) {
                float o = acc[i][j] + bia[j];
                o = (o - mean[j]) * scl[j] + betc[j];
                o = fmaxf(o, 0.f);
                op[j] = xa[j] + HSTEP * o;
            }
            *(float4*)(d_g1 + r * 64 + cc) = ov;
            *(float4*)(SOUT + (rr + i) * 68 + cc) = ov;
        }
    }
    // stage phi chunk
    for (int e = t; e < 2048; e += 256) {
        int r = e >> 5, dd = e & 31;
        SPHI[r * 33 + dd] = d_phi[r0 * 32 + e];
    }
    __syncthreads();

    // partial M1 = phi_chunk^T @ out_chunk
    int d2 = t & 31, cb = (t >> 5) * 8;
    float macc[8] = {0.f, 0.f, 0.f, 0.f, 0.f, 0.f, 0.f, 0.f};
#pragma unroll 8
    for (int r2 = 0; r2 < 64; r2++) {
        float pd = SPHI[r2 * 33 + d2];
        float4 o0 = *(const float4*)(SOUT + r2 * 68 + cb);
        float4 o1 = *(const float4*)(SOUT + r2 * 68 + cb + 4);
        macc[0] = fmaf(pd, o0.x, macc[0]); macc[1] = fmaf(pd, o0.y, macc[1]);
        macc[2] = fmaf(pd, o0.z, macc[2]); macc[3] = fmaf(pd, o0.w, macc[3]);
        macc[4] = fmaf(pd, o1.x, macc[4]); macc[5] = fmaf(pd, o1.y, macc[5]);
        macc[6] = fmaf(pd, o1.z, macc[6]); macc[7] = fmaf(pd, o1.w, macc[7]);
    }
    {
        float* Mb = d_Mbuf[1] + b * 2048 + d2 * 64 + cb;
#pragma unroll
        for (int q = 0; q < 8; q++) atomicAdd(&Mb[q], macc[q]);
    }

    __threadfence();
    __syncthreads();
    if (t == 0) s_old = atomicAdd(&d_cnt2[b], 1u);
    __syncthreads();
    if (s_old != 48u) return;

    // ---- TAIL: MW1 = (lam/N) * M1 @ W1 ----
    __threadfence();
    float* SW = sm2;            // 64*68
    float* SM = sm2 + 6528;     // 2048
    const float* W1 = Wst + 4096;
    for (int e = t; e < 1024; e += 256) {
        int k = e >> 4, c4 = (e & 15) * 4;
        *(float4*)(SW + k * 68 + c4) = ((const float4*)W1)[e];
    }
    for (int e = t; e < 2048; e += 256) {
        SM[e] = d_Mbuf[1][b * 2048 + e];
        d_Mbuf[1][b * 2048 + e] = 0.f;
    }
    if (t == 0) d_cnt2[b] = 0u;
    __syncthreads();

    int dd = t >> 3, c0 = (t & 7) * 8;
    float a2[8] = {0.f, 0.f, 0.f, 0.f, 0.f, 0.f, 0.f, 0.f};
#pragma unroll 8
    for (int c = 0; c < 64; c++) {
        float m = SM[dd * 64 + c];
        float4 w0 = *(const float4*)(SW + c * 68 + c0);
        float4 w1v = *(const float4*)(SW + c * 68 + c0 + 4);
        a2[0] = fmaf(m, w0.x, a2[0]); a2[1] = fmaf(m, w0.y, a2[1]);
        a2[2] = fmaf(m, w0.z, a2[2]); a2[3] = fmaf(m, w0.w, a2[3]);
        a2[4] = fmaf(m, w1v.x, a2[4]); a2[5] = fmaf(m, w1v.y, a2[5]);
        a2[6] = fmaf(m, w1v.z, a2[6]); a2[7] = fmaf(m, w1v.w, a2[7]);
    }
    float* o = d_MW[1] + b * 2048 + dd * 64 + c0;
    const float sc = LAMF * INVN;
#pragma unroll
    for (int q = 0; q < 8; q++) o[q] = sc * a2[q];
}

// ===========================================================================
// K3: apply iteration 1 -> d_out (no fusion tail).
__global__ void __launch_bounds__(256) k_apply_final(
        const float* __restrict__ x,
        const float* __restrict__ Wst, const float* __restrict__ bst,
        const float* __restrict__ gam, const float* __restrict__ bet,
        const float* __restrict__ mmean, const float* __restrict__ mvar,
        float* __restrict__ out) {
    __shared__ float sAt[96 * 68];
    __shared__ float sB[96 * 68];
    __shared__ float ss[64];
    __shared__ float sps[32];

    int t  = threadIdx.x;
    int r0 = blockIdx.x * 64;
    int b  = blockIdx.x / 49;

#pragma unroll
    for (int j = 0; j < 2; j++) {
        int e = t + j * 256;
        int r = e >> 3, dd = (e & 7) * 4;
        float4 v = ((const float4*)(d_theta + r0 * 32))[e];
        sAt[(dd + 0) * 68 + r] = v.x;
        sAt[(dd + 1) * 68 + r] = v.y;
        sAt[(dd + 2) * 68 + r] = v.z;
        sAt[(dd + 3) * 68 + r] = v.w;
    }
    const float* MWi = d_MW[1] + b * 2048;
    const float* Wi  = Wst + 4096;
#pragma unroll
    for (int j = 0; j < 6; j++) {
        int e = t + j * 256;
        if (e < 512) {
            int k = e >> 4, c4 = (e & 15) * 4;
            *(float4*)(sB + k * 68 + c4) = ((const float4*)MWi)[e];
        } else {
            int e2 = e - 512;
            int k = e2 >> 4, c4 = (e2 & 15) * 4;
            *(float4*)(sB + (32 + k) * 68 + c4) = ((const float4*)Wi)[e2];
        }
    }
    if (t < 32) sps[t] = d_phisum[b * 32 + t];
    __syncthreads();

    if (t < 64) {
        float a = 0.f;
#pragma unroll
        for (int k = 0; k < 32; k++) a = fmaf(sAt[k * 68 + t], sps[k], a);
        ss[t] = a * (-LAMF * INVN);
    }
    __syncthreads();

#pragma unroll
    for (int j = 0; j < 4; j++) {
        int e = t + j * 256;
        int r = e >> 4, c4 = (e & 15) * 4;
        float4 v = ((const float4*)(d_g1 + r0 * 64))[e];
        float sc = ss[r];
        sAt[(32 + c4 + 0) * 68 + r] = v.x * sc;
        sAt[(32 + c4 + 1) * 68 + r] = v.y * sc;
        sAt[(32 + c4 + 2) * 68 + r] = v.z * sc;
        sAt[(32 + c4 + 3) * 68 + r] = v.w * sc;
    }
    __syncthreads();

    int tx = t & 15, ty = t >> 4;
    int rr = ty * 4, cc = tx * 4;
    float acc[4][4];
#pragma unroll
    for (int i = 0; i < 4; i++)
#pragma unroll
        for (int j = 0; j < 4; j++) acc[i][j] = 0.f;

#pragma unroll 8
    for (int k = 0; k < 96; k++) {
        float4 a = *(const float4*)(sAt + k * 68 + rr);
        float4 bv = *(const float4*)(sB + k * 68 + cc);
        acc[0][0] = fmaf(a.x, bv.x, acc[0][0]); acc[0][1] = fmaf(a.x, bv.y, acc[0][1]);
        acc[0][2] = fmaf(a.x, bv.z, acc[0][2]); acc[0][3] = fmaf(a.x, bv.w, acc[0][3]);
        acc[1][0] = fmaf(a.y, bv.x, acc[1][0]); acc[1][1] = fmaf(a.y, bv.y, acc[1][1]);
        acc[1][2] = fmaf(a.y, bv.z, acc[1][2]); acc[1][3] = fmaf(a.y, bv.w, acc[1][3]);
        acc[2][0] = fmaf(a.z, bv.x, acc[2][0]); acc[2][1] = fmaf(a.z, bv.y, acc[2][1]);
        acc[2][2] = fmaf(a.z, bv.z, acc[2][2]); acc[2][3] = fmaf(a.z, bv.w, acc[2][3]);
        acc[3][0] = fmaf(a.w, bv.x, acc[3][0]); acc[3][1] = fmaf(a.w, bv.y, acc[3][1]);
        acc[3][2] = fmaf(a.w, bv.z, acc[3][2]); acc[3][3] = fmaf(a.w, bv.w, acc[3][3]);
    }

    float4 bias = *(const float4*)(bst + 64 + cc);
    float4 gm   = *(const float4*)(gam + 64 + cc);
    float4 bt4  = *(const float4*)(bet + 64 + cc);
    float4 mmv  = *(const float4*)(mmean + 64 + cc);
    float4 mv   = *(const float4*)(mvar + 64 + cc);
    float scl[4] = { gm.x * rsqrtf(mv.x + BNEPS), gm.y * rsqrtf(mv.y + BNEPS),
                     gm.z * rsqrtf(mv.z + BNEPS), gm.w * rsqrtf(mv.w + BNEPS) };
    float bia[4]  = { bias.x, bias.y, bias.z, bias.w };
    float mean[4] = { mmv.x, mmv.y, mmv.z, mmv.w };
    float betc[4] = { bt4.x, bt4.y, bt4.z, bt4.w };

#pragma unroll
    for (int i = 0; i < 4; i++) {
        int r = r0 + rr + i;
        float4 xv = *(const float4*)(x + r * 64 + cc);
        float xa[4] = { xv.x, xv.y, xv.z, xv.w };
        float4 ov;
        float* op = (float*)&ov;
#pragma unroll
        for (int j = 0; j < 4; j++) {
            float o = acc[i][j] + bia[j];
            o = (o - mean[j]) * scl[j] + betc[j];
            o = fmaxf(o, 0.f);
            op[j] = xa[j] + HSTEP * o;
        }
        *(float4*)(out + r * 64 + cc) = ov;
    }
}

// ---------------------------------------------------------------------------
extern "C" void kernel_launch(void* const* d_in, const int* in_sizes, int n_in,
                              void* d_out, int out_size) {
    const float* x     = (const float*)d_in[0];
    const float* Wt    = (const float*)d_in[1];
    const float* bt    = (const float*)d_in[2];
    const float* Wp    = (const float*)d_in[3];
    const float* bp    = (const float*)d_in[4];
    const float* Wst   = (const float*)d_in[5];
    const float* bst   = (const float*)d_in[6];
    const float* gam   = (const float*)d_in[7];
    const float* bet   = (const float*)d_in[8];
    const float* mmean = (const float*)d_in[9];
    const float* mvar  = (const float*)d_in[10];
    float* out = (float*)d_out;

    k_front<<<784, 256>>>(x, Wt, bt, Wp, bp, Wst);
    k_apply_fused<<<392, 256>>>(x, Wst, bst, gam, bet, mmean, mvar);
    k_apply_final<<<392, 256>>>(x, Wst, bst, gam, bet, mmean, mvar, out);
}

// round 5
// speedup vs baseline: 1.7482x; 1.7482x over previous
#include <cuda_runtime.h>

#define Bb     8
#define Nn     3136
#define Cc     64
#define CI     32
#define BNROWS 25088          // Bb * Nn
#define LAMF   0.1f
#define HSTEP  0.05f
#define BNEPS  1e-3f
#define INVN   (1.0f / 3136.0f)

// ---- scratch (static device globals; no allocation) ----
__device__ float d_theta[BNROWS * CI];
__device__ float d_phi[BNROWS * CI];
__device__ float d_phisum[Bb * CI];
__device__ float d_pspart[784 * CI];     // per-block phi-sum partials (plain stores)
__device__ float d_M[2][Bb * 2048];      // phi^T g per iter; zeroed inside k_theta_phi
__device__ float d_g1[BNROWS * Cc];

// ===========================================================================
// K1: theta/phi = x @ Wt/Wp + bias; per-block phi-sum partials (no atomics to
// global); first 32 blocks also zero d_M for this call (d_M untouched here).
__global__ void __launch_bounds__(256) k_theta_phi(
        const float* __restrict__ x,
        const float* __restrict__ Wt, const float* __restrict__ bt,
        const float* __restrict__ Wp, const float* __restrict__ bp) {
    __shared__ float sx[32 * 64];
    __shared__ float sWt[32 * 68];
    __shared__ float sWp[32 * 68];
    __shared__ float sp[32];
    int t  = threadIdx.x;
    int gb = blockIdx.x;
    int r0 = gb * 32;

    if (gb < 32) {   // zero both M buffers: 8192 float4 total
        float4 z = make_float4(0.f, 0.f, 0.f, 0.f);
        ((float4*)d_M)[gb * 256 + t] = z;
    }
    {
        const float4* src = (const float4*)(x + r0 * 64);
        ((float4*)sx)[t]       = src[t];
        ((float4*)sx)[t + 256] = src[t + 256];
    }
    for (int e = t; e < 2048; e += 256) {   // weights transposed
        int k = e >> 5, d = e & 31;
        sWt[d * 68 + k] = Wt[e];
        sWp[d * 68 + k] = Wp[e];
    }
    if (t < 32) sp[t] = 0.f;
    __syncthreads();

    int w = t >> 5, d = t & 31;
    float th[4], ph[4];
    float bt_d = bt[d], bp_d = bp[d];
#pragma unroll
    for (int j = 0; j < 4; j++) { th[j] = bt_d; ph[j] = bp_d; }

    const float* xr = sx + w * 4 * 64;
    const float* wt = sWt + d * 68;
    const float* wp = sWp + d * 68;
#pragma unroll
    for (int k = 0; k < 64; k += 4) {
        float4 a = *(const float4*)(wt + k);
        float4 b = *(const float4*)(wp + k);
#pragma unroll
        for (int j = 0; j < 4; j++) {
            float4 xv = *(const float4*)(xr + j * 64 + k);
            th[j] = fmaf(xv.x, a.x, th[j]); th[j] = fmaf(xv.y, a.y, th[j]);
            th[j] = fmaf(xv.z, a.z, th[j]); th[j] = fmaf(xv.w, a.w, th[j]);
            ph[j] = fmaf(xv.x, b.x, ph[j]); ph[j] = fmaf(xv.y, b.y, ph[j]);
            ph[j] = fmaf(xv.z, b.z, ph[j]); ph[j] = fmaf(xv.w, b.w, ph[j]);
        }
    }
    int r = r0 + w * 4;
    float phs = 0.f;
#pragma unroll
    for (int j = 0; j < 4; j++) {
        d_theta[(r + j) * 32 + d] = th[j];
        d_phi[(r + j) * 32 + d]   = ph[j];
        phs += ph[j];
    }
    atomicAdd(&sp[d], phs);
    __syncthreads();
    if (t < 32) d_pspart[gb * 32 + t] = sp[t];
}

// ===========================================================================
// K2/K4: M[iter][b] += phi[b]^T @ g[b] (atomics; d_M pre-zeroed in K1).
// chunk-0 blocks also finalize d_phisum from partials (reads prior-kernel data).
__global__ void __launch_bounds__(256) k_reduceM(const float* __restrict__ x,
                                                 int use_g1, int iter) {
    const float* g = use_g1 ? d_g1 : x;
    __shared__ float sph[2][16 * 32];
    __shared__ float sg[2][16 * 64];
    int t     = threadIdx.x;
    int b     = blockIdx.x / 49;
    int chunk = blockIdx.x % 49;
    int row0  = b * Nn + chunk * 64;

    if (chunk == 0 && t < 32) {   // finalize phisum (idempotent)
        float a = 0.f;
        for (int j = 0; j < 98; j++) a += d_pspart[(b * 98 + j) * 32 + t];
        d_phisum[b * 32 + t] = a;
    }

    int d = t & 31, cb = (t >> 5) * 8;
    float acc[8] = {0.f, 0.f, 0.f, 0.f, 0.f, 0.f, 0.f, 0.f};

    const float4* phg = (const float4*)(d_phi + row0 * 32);
    const float4* gg  = (const float4*)(g + row0 * 64);

    if (t < 128) ((float4*)sph[0])[t] = phg[t];
    ((float4*)sg[0])[t] = gg[t];
    __syncthreads();

#pragma unroll
    for (int tt = 0; tt < 4; tt++) {
        int cur = tt & 1, nxt = cur ^ 1;
        float4 pre_p, pre_g;
        if (tt < 3) {
            if (t < 128) pre_p = phg[(tt + 1) * 128 + t];
            pre_g = gg[(tt + 1) * 256 + t];
        }
        const float* P = sph[cur];
        const float* G = sg[cur];
#pragma unroll
        for (int j = 0; j < 16; j++) {
            float pd = P[j * 32 + d];
            float4 g0 = *(const float4*)(G + j * 64 + cb);
            float4 g1v = *(const float4*)(G + j * 64 + cb + 4);
            acc[0] = fmaf(pd, g0.x, acc[0]);  acc[1] = fmaf(pd, g0.y, acc[1]);
            acc[2] = fmaf(pd, g0.z, acc[2]);  acc[3] = fmaf(pd, g0.w, acc[3]);
            acc[4] = fmaf(pd, g1v.x, acc[4]); acc[5] = fmaf(pd, g1v.y, acc[5]);
            acc[6] = fmaf(pd, g1v.z, acc[6]); acc[7] = fmaf(pd, g1v.w, acc[7]);
        }
        if (tt < 3) {
            if (t < 128) ((float4*)sph[nxt])[t] = pre_p;
            ((float4*)sg[nxt])[t] = pre_g;
        }
        __syncthreads();
    }
    float* Mb = d_M[iter] + b * 2048 + d * 64 + cb;
#pragma unroll
    for (int q = 0; q < 8; q++) atomicAdd(&Mb[q], acc[q]);
}

// ===========================================================================
// K3/K5: two-phase apply, no MW precompute needed:
//   phase1: raw = theta @ M  (K=32);  fg = (lam/N)*raw - (s/N)*g
//   phase2: o = fg @ W + bias; BN; ReLU; out = x + 0.05*o
// 64 rows/block, 4x4 register tile both phases. smem reuse keeps it < 36 KB.
__global__ void __launch_bounds__(256) k_apply(
        const float* __restrict__ x,
        const float* __restrict__ Wst, const float* __restrict__ bst,
        const float* __restrict__ gam, const float* __restrict__ bet,
        const float* __restrict__ mmean, const float* __restrict__ mvar,
        int iter, int gin_is_g1, float* __restrict__ out_ext, int out_is_g1) {
    const float* gin = gin_is_g1 ? d_g1 : x;
    float* out       = out_is_g1 ? d_g1 : out_ext;

    __shared__ float sm[8800];
    float* sAt  = sm;          // theta^T [k=32][row 64] pad 68   (2176)
    float* sM   = sm + 2176;   // M [k=32][col 64] pad 68          (2176)
    float* sW   = sm + 4352;   // W [k=64][col 64] pad 68          (4352)
    float* sfgT = sm;          // fg^T [k=64][row 64] pad 68, overlays sAt+sM
    float* ss   = sm + 8704;   // 64
    float* sps  = sm + 8768;   // 32

    int t  = threadIdx.x;
    int r0 = blockIdx.x * 64;
    int b  = blockIdx.x / 49;

    // stage theta^T
#pragma unroll
    for (int j = 0; j < 2; j++) {
        int e = t + j * 256;
        int r = e >> 3, dd = (e & 7) * 4;
        float4 v = ((const float4*)(d_theta + r0 * 32))[e];
        sAt[(dd + 0) * 68 + r] = v.x;
        sAt[(dd + 1) * 68 + r] = v.y;
        sAt[(dd + 2) * 68 + r] = v.z;
        sAt[(dd + 3) * 68 + r] = v.w;
    }
    // stage M
    const float* Mi = d_M[iter] + b * 2048;
#pragma unroll
    for (int j = 0; j < 2; j++) {
        int e = t + j * 256;
        int k = e >> 4, c4 = (e & 15) * 4;
        *(float4*)(sM + k * 68 + c4) = ((const float4*)Mi)[e];
    }
    // stage W
    const float* Wi = Wst + iter * 4096;
#pragma unroll
    for (int j = 0; j < 4; j++) {
        int e = t + j * 256;
        int k = e >> 4, c4 = (e & 15) * 4;
        *(float4*)(sW + k * 68 + c4) = ((const float4*)Wi)[e];
    }
    if (t < 32) sps[t] = d_phisum[b * 32 + t];
    __syncthreads();

    if (t < 64) {   // -(s/N) per row, s = LAM * theta . phisum
        float a = 0.f;
#pragma unroll
        for (int k = 0; k < 32; k++) a = fmaf(sAt[k * 68 + t], sps[k], a);
        ss[t] = a * (-LAMF * INVN);
    }
    __syncthreads();

    int tx = t & 15, ty = t >> 4;
    int rr = ty * 4, cc = tx * 4;

    // ---- phase 1: raw = theta @ M (K=32) ----
    float fg[4][4];
#pragma unroll
    for (int i = 0; i < 4; i++)
#pragma unroll
        for (int j = 0; j < 4; j++) fg[i][j] = 0.f;

#pragma unroll 8
    for (int k = 0; k < 32; k++) {
        float4 a  = *(const float4*)(sAt + k * 68 + rr);
        float4 bv = *(const float4*)(sM + k * 68 + cc);
        fg[0][0] = fmaf(a.x, bv.x, fg[0][0]); fg[0][1] = fmaf(a.x, bv.y, fg[0][1]);
        fg[0][2] = fmaf(a.x, bv.z, fg[0][2]); fg[0][3] = fmaf(a.x, bv.w, fg[0][3]);
        fg[1][0] = fmaf(a.y, bv.x, fg[1][0]); fg[1][1] = fmaf(a.y, bv.y, fg[1][1]);
        fg[1][2] = fmaf(a.y, bv.z, fg[1][2]); fg[1][3] = fmaf(a.y, bv.w, fg[1][3]);
        fg[2][0] = fmaf(a.z, bv.x, fg[2][0]); fg[2][1] = fmaf(a.z, bv.y, fg[2][1]);
        fg[2][2] = fmaf(a.z, bv.z, fg[2][2]); fg[2][3] = fmaf(a.z, bv.w, fg[2][3]);
        fg[3][0] = fmaf(a.w, bv.x, fg[3][0]); fg[3][1] = fmaf(a.w, bv.y, fg[3][1]);
        fg[3][2] = fmaf(a.w, bv.z, fg[3][2]); fg[3][3] = fmaf(a.w, bv.w, fg[3][3]);
    }
    // fg = (lam/N)*raw + ssneg*g
    const float c1 = LAMF * INVN;
#pragma unroll
    for (int i = 0; i < 4; i++) {
        float sneg = ss[rr + i];
        float4 gv = *(const float4*)(gin + (r0 + rr + i) * 64 + cc);
        fg[i][0] = fmaf(sneg, gv.x, c1 * fg[i][0]);
        fg[i][1] = fmaf(sneg, gv.y, c1 * fg[i][1]);
        fg[i][2] = fmaf(sneg, gv.z, c1 * fg[i][2]);
        fg[i][3] = fmaf(sneg, gv.w, c1 * fg[i][3]);
    }
    __syncthreads();   // sAt/sM fully read; reuse region as sfgT

    // store fg transposed: sfgT[k=col][row]
#pragma unroll
    for (int j = 0; j < 4; j++) {
        float4 v = make_float4(fg[0][j], fg[1][j], fg[2][j], fg[3][j]);
        *(float4*)(sfgT + (cc + j) * 68 + rr) = v;
    }
    __syncthreads();

    // ---- phase 2: o = fg @ W (K=64) ----
    float acc[4][4];
#pragma unroll
    for (int i = 0; i < 4; i++)
#pragma unroll
        for (int j = 0; j < 4; j++) acc[i][j] = 0.f;

#pragma unroll 8
    for (int k = 0; k < 64; k++) {
        float4 a  = *(const float4*)(sfgT + k * 68 + rr);
        float4 bv = *(const float4*)(sW + k * 68 + cc);
        acc[0][0] = fmaf(a.x, bv.x, acc[0][0]); acc[0][1] = fmaf(a.x, bv.y, acc[0][1]);
        acc[0][2] = fmaf(a.x, bv.z, acc[0][2]); acc[0][3] = fmaf(a.x, bv.w, acc[0][3]);
        acc[1][0] = fmaf(a.y, bv.x, acc[1][0]); acc[1][1] = fmaf(a.y, bv.y, acc[1][1]);
        acc[1][2] = fmaf(a.y, bv.z, acc[1][2]); acc[1][3] = fmaf(a.y, bv.w, acc[1][3]);
        acc[2][0] = fmaf(a.z, bv.x, acc[2][0]); acc[2][1] = fmaf(a.z, bv.y, acc[2][1]);
        acc[2][2] = fmaf(a.z, bv.z, acc[2][2]); acc[2][3] = fmaf(a.z, bv.w, acc[2][3]);
        acc[3][0] = fmaf(a.w, bv.x, acc[3][0]); acc[3][1] = fmaf(a.w, bv.y, acc[3][1]);
        acc[3][2] = fmaf(a.w, bv.z, acc[3][2]); acc[3][3] = fmaf(a.w, bv.w, acc[3][3]);
    }

    // epilogue: bias, BN, ReLU, residual (last == x always)
    float4 bias = *(const float4*)(bst + iter * 64 + cc);
    float4 gm   = *(const float4*)(gam + iter * 64 + cc);
    float4 bt4  = *(const float4*)(bet + iter * 64 + cc);
    float4 mmv  = *(const float4*)(mmean + iter * 64 + cc);
    float4 mv   = *(const float4*)(mvar + iter * 64 + cc);
    float scl[4]  = { gm.x * rsqrtf(mv.x + BNEPS), gm.y * rsqrtf(mv.y + BNEPS),
                      gm.z * rsqrtf(mv.z + BNEPS), gm.w * rsqrtf(mv.w + BNEPS) };
    float bia[4]  = { bias.x, bias.y, bias.z, bias.w };
    float mean[4] = { mmv.x, mmv.y, mmv.z, mmv.w };
    float betc[4] = { bt4.x, bt4.y, bt4.z, bt4.w };

#pragma unroll
    for (int i = 0; i < 4; i++) {
        int r = r0 + rr + i;
        float4 xv = *(const float4*)(x + r * 64 + cc);
        float xa[4] = { xv.x, xv.y, xv.z, xv.w };
        float4 ov;
        float* op = (float*)&ov;
#pragma unroll
        for (int j = 0; j < 4; j++) {
            float o = acc[i][j] + bia[j];
            o = (o - mean[j]) * scl[j] + betc[j];
            o = fmaxf(o, 0.f);
            op[j] = xa[j] + HSTEP * o;
        }
        *(float4*)(out + r * 64 + cc) = ov;
    }
}

// ---------------------------------------------------------------------------
extern "C" void kernel_launch(void* const* d_in, const int* in_sizes, int n_in,
                              void* d_out, int out_size) {
    const float* x     = (const float*)d_in[0];
    const float* Wt    = (const float*)d_in[1];
    const float* bt    = (const float*)d_in[2];
    const float* Wp    = (const float*)d_in[3];
    const float* bp    = (const float*)d_in[4];
    const float* Wst   = (const float*)d_in[5];
    const float* bst   = (const float*)d_in[6];
    const float* gam   = (const float*)d_in[7];
    const float* bet   = (const float*)d_in[8];
    const float* mmean = (const float*)d_in[9];
    const float* mvar  = (const float*)d_in[10];
    float* out = (float*)d_out;

    k_theta_phi<<<BNROWS / 32, 256>>>(x, Wt, bt, Wp, bp);

    k_reduceM<<<Bb * 49, 256>>>(x, 0, 0);
    k_apply<<<BNROWS / 64, 256>>>(x, Wst, bst, gam, bet, mmean, mvar, 0, 0, nullptr, 1);

    k_reduceM<<<Bb * 49, 256>>>(x, 1, 1);
    k_apply<<<BNROWS / 64, 256>>>(x, Wst, bst, gam, bet, mmean, mvar, 1, 1, out, 0);
}